// round 5
// baseline (speedup 1.0000x reference)
#include <cuda_runtime.h>
#include <math.h>

#define NBATCH 16
#define NANCH  3
#define FS     64
#define NPIX   4096
#define NLAB   50
#define NCLS   80
#define NCH    85
#define CLSBLK (NBATCH*NLAB)        // 800 class-loss blocks (one per label)
#define CONVBLK 256                 // 16 blocks/batch * 16 batches
#define TOTBLK (CLSBLK + CONVBLK)   // 1056

// ---------------- device scratch ----------------
__device__ float4       g_part[TOTBLK];   // per-block partials: x=xy y=wh z=obj w=cls
__device__ unsigned int g_ticket;         // zero-initialized; reset by last block

__constant__ float c_RW[9] = {1.25f,2.0f,4.125f,3.75f,7.75f,7.375f,14.5f,19.5f,46.625f};
__constant__ float c_RH[9] = {1.625f,3.75f,2.875f,7.625f,5.625f,14.875f,11.25f,24.75f,40.75f};

__device__ __forceinline__ float sigm(float x){ return 1.0f/(1.0f + expf(-x)); }

// softplus(o) = max(o,0) + log1p(exp(-|o|));  BCE(sigmoid(o), t) = softplus(o) - t*o
__device__ __forceinline__ float sp(float o){
    return fmaxf(o, 0.0f) + log1pf(expf(-fabsf(o)));
}

__device__ __forceinline__ float warpsum(float v){
    #pragma unroll
    for (int o = 16; o; o >>= 1) v += __shfl_down_sync(0xffffffffu, v, o);
    return v;
}

// packed fp32x2 helpers (Blackwell)
__device__ __forceinline__ unsigned long long packff(float a, float b){
    unsigned long long r;
    asm("mov.b64 %0, {%1, %2};" : "=l"(r) : "r"(__float_as_uint(a)), "r"(__float_as_uint(b)));
    return r;
}
__device__ __forceinline__ void unpackff(unsigned long long v, float& a, float& b){
    unsigned int lo, hi;
    asm("mov.b64 {%0, %1}, %2;" : "=r"(lo), "=r"(hi) : "l"(v));
    a = __uint_as_float(lo); b = __uint_as_float(hi);
}
#define FMA2(acc, a, b) asm("fma.rn.f32x2 %0, %1, %2, %0;" : "+l"(acc) : "l"(a), "l"(b))

// candidate cell index for one label (or -1)
__device__ __forceinline__ int label_idx(const float* __restrict__ L,
                                         float& tx, float& ty, float& tw, float& th,
                                         int& bi){
    float cls = L[0], x = L[1], y = L[2], w = L[3], h = L[4];
    tx = x*FS; ty = y*FS; tw = w*FS; th = h*FS;
    float best = -1e30f; bi = 0;
    #pragma unroll
    for (int n = 0; n < 9; n++){
        float inter = fminf(tw, c_RW[n]) * fminf(th, c_RH[n]);
        float uni   = tw*th + c_RW[n]*c_RH[n] - inter;
        float iou   = inter/uni;
        if (iou > best){ best = iou; bi = n; }
    }
    bool valid = (cls + x + y + w + h) > 0.0f;
    if (!(valid && bi < NANCH)) return -1;
    int ti = (int)tx, tj = (int)ty;
    return (bi<<12)|(tj<<6)|ti;
}

// ---------------- single fused kernel ----------------
__global__ __launch_bounds__(256) void k_fused(const float* __restrict__ xin,
                                               const float* __restrict__ labels,
                                               const float* __restrict__ conv_w,
                                               const float* __restrict__ conv_b,
                                               float* __restrict__ out){
    // shared state (branch-disjoint usage overlaps safely where noted)
    __shared__ __align__(16) float Ws[256*16];      // conv path only
    __shared__ float4 s_tb[NLAB];
    __shared__ float  s_ta[NLAB];
    __shared__ int    s_idx[NLAB];
    __shared__ int    s_fidx[NLAB];
    __shared__ float4 s_l4[NLAB];
    __shared__ float  s_lt[NLAB];
    __shared__ float  s_bias[16];
    __shared__ float  s_red[8][3];
    __shared__ float  xs[256];                       // cls path
    __shared__ float  s_wred[8];
    __shared__ int    s_win;
    __shared__ int    s_last;
    __shared__ double sr[4];

    int tid = threadIdx.x;
    float4 partial = make_float4(0.f, 0.f, 0.f, 0.f);   // meaningful on tid 0 only

    if (blockIdx.x < CLSBLK){
        // ================= class-loss block for label (b, k) =================
        int mb = blockIdx.x;
        int b  = mb / NLAB, k = mb - b*NLAB;

        if (tid < NLAB){
            float tx,ty,tw,th; int bi;
            s_idx[tid] = label_idx(labels + (size_t)(b*NLAB + tid)*5, tx,ty,tw,th, bi);
        }
        __syncthreads();
        if (tid == 0){
            int idx = s_idx[k];
            if (idx >= 0)
                for (int j = k+1; j < NLAB; j++) if (s_idx[j] == idx) { idx = -1; break; }
            s_win = idx;
        }
        __syncthreads();
        int idx = s_win;
        if (idx >= 0){
            int a = idx >> 12, pix = idx & 4095;
            int cls = (int)labels[(size_t)(b*NLAB + k)*5];

            xs[tid] = __ldg(xin + ((size_t)(b*256 + tid))*NPIX + pix);
            __syncthreads();

            int w = tid >> 5, lane = tid & 31;   // 8 warps x 10 classes
            float lc = 0.0f;
            #pragma unroll 2
            for (int t = 0; t < 10; t++){
                int c = w + (t<<3);
                int o = a*NCH + 5 + c;
                const float* wr = conv_w + (size_t)o*256;
                float s = 0.0f;
                #pragma unroll
                for (int i = 0; i < 8; i++) s += xs[lane + (i<<5)]*__ldg(wr + lane + (i<<5));
                s = warpsum(s);
                if (lane == 0){
                    s += conv_b[o];
                    lc += sp(s) - ((c == cls) ? s : 0.0f);   // BCE(sigm(s), t)
                }
            }
            if (lane == 0) s_wred[w] = lc;
            __syncthreads();
            if (tid == 0){
                float v = 0.0f;
                #pragma unroll
                for (int q = 0; q < 8; q++) v += s_wred[q];
                partial.w = v;
            }
        }
    } else {
        // ================= conv + obj/xy/wh block =================
        int cb  = (int)blockIdx.x - CLSBLK;
        int b   = cb >> 4;
        int pix = ((cb & 15) << 8) + tid;

        for (int i = tid; i < 15*256; i += 256){
            int s = i >> 8, c = i & 255;
            int a = s/5, j = s - a*5;
            Ws[c*16 + s] = conv_w[(a*NCH + j)*256 + c];
        }
        Ws[tid*16 + 15] = 0.0f;
        if (tid >= 224 && tid < 239){ int s = tid-224; int a = s/5; s_bias[s] = conv_b[a*NCH + (s - a*5)]; }
        if (tid == 239) s_bias[15] = 0.0f;
        if (tid < NLAB){
            const float* L = labels + (size_t)(b*NLAB + tid)*5;
            float tx,ty,tw,th; int bi;
            int idx = label_idx(L, tx,ty,tw,th, bi);
            s_idx[tid] = idx;
            s_tb[tid]  = make_float4(tx - tw*0.5f, ty - th*0.5f, tx + tw*0.5f, ty + th*0.5f);
            s_ta[tid]  = tw*th;
            int ti = (int)tx, tj = (int)ty;
            int sb = (bi < NANCH) ? bi : 0;
            s_l4[tid] = make_float4(tx - (float)ti, ty - (float)tj,
                                    logf(tw / c_RW[sb] + 1e-16f),
                                    logf(th / c_RH[sb] + 1e-16f));
            s_lt[tid] = 2.0f - tw*th*(1.0f/(float)(FS*FS));
        }
        __syncthreads();

        if (tid < NLAB){
            int idx = s_idx[tid];
            if (idx >= 0)
                for (int j = tid+1; j < NLAB; j++) if (s_idx[j] == idx) { idx = -1; break; }
            s_fidx[tid] = idx;
        }

        unsigned long long accd[8];
        #pragma unroll
        for (int p = 0; p < 8; p++) accd[p] = packff(s_bias[2*p], s_bias[2*p+1]);

        const float* xp = xin + (size_t)b*256*NPIX + pix;
        const ulonglong2* W2 = reinterpret_cast<const ulonglong2*>(Ws);
        #pragma unroll 4
        for (int c = 0; c < 256; c++){
            float x = __ldg(xp + (size_t)c*NPIX);
            unsigned long long xd = packff(x, x);
            ulonglong2 q0 = W2[c*4+0], q1 = W2[c*4+1], q2 = W2[c*4+2], q3 = W2[c*4+3];
            FMA2(accd[0], xd, q0.x); FMA2(accd[1], xd, q0.y);
            FMA2(accd[2], xd, q1.x); FMA2(accd[3], xd, q1.y);
            FMA2(accd[4], xd, q2.x); FMA2(accd[5], xd, q2.y);
            FMA2(accd[6], xd, q3.x); FMA2(accd[7], xd, q3.y);
        }
        float acc[16];
        #pragma unroll
        for (int p = 0; p < 8; p++) unpackff(accd[p], acc[2*p], acc[2*p+1]);
        __syncthreads();   // s_fidx visible

        const float MAW[3] = {1.25f, 2.0f, 4.125f};
        const float MAH[3] = {1.625f, 3.75f, 2.875f};
        float fw = (float)(pix & 63);
        float fh = (float)(pix >> 6);
        float p0a[3], p1a[3];
        float ax0[3], ay0[3], ax1[3], ay1[3], areaA[3];
        #pragma unroll
        for (int a = 0; a < 3; a++){
            float o0 = acc[a*5+0], o1 = acc[a*5+1];
            float o2 = acc[a*5+2], o3 = acc[a*5+3];
            p0a[a] = sigm(o0); p1a[a] = sigm(o1);
            float pw = expf(o2)*MAW[a], ph = expf(o3)*MAH[a];
            float px = p0a[a] + fw, py = p1a[a] + fh;
            areaA[a] = pw*ph;
            ax0[a] = px - pw*0.5f; ay0[a] = py - ph*0.5f;
            ax1[a] = px + pw*0.5f; ay1[a] = py + ph*0.5f;
        }

        int ign = 0;
        int msl[3] = {-1,-1,-1};
        for (int kk = 0; kk < NLAB; kk++){
            float4 t = s_tb[kk];
            float ta = s_ta[kk];
            #pragma unroll
            for (int a = 0; a < 3; a++){
                float iw = fmaxf(fminf(ax1[a], t.z) - fmaxf(ax0[a], t.x), 0.0f);
                float ih = fmaxf(fminf(ay1[a], t.w) - fmaxf(ay0[a], t.y), 0.0f);
                float inter = iw*ih;
                float den   = areaA[a] + ta - inter;
                ign |= (inter > 0.7f*den) << a;
            }
            int e = s_fidx[kk];
            if (e >= 0 && (e & 4095) == pix) msl[e >> 12] = kk;
        }

        float lobj = 0.0f, lxy = 0.0f, lwh = 0.0f;
        #pragma unroll
        for (int a = 0; a < 3; a++){
            float o4 = acc[a*5+4];
            int slot = msl[a];
            if (slot >= 0){
                lobj += sp(o4) - o4;                        // BCE(sigm(o4), 1)
                float4 d = s_l4[slot];
                float ts = s_lt[slot];
                float o0 = acc[a*5+0], o1 = acc[a*5+1];
                lxy += (sp(o0) - d.x*o0 + sp(o1) - d.y*o1)*ts;
                float dw = acc[a*5+2] - d.z, dh = acc[a*5+3] - d.w;
                lwh += (dw*dw + dh*dh)*0.5f*ts;
            } else if (!((ign >> a) & 1)){
                lobj += sp(o4);                             // BCE(sigm(o4), 0)
            }
        }

        lxy = warpsum(lxy); lwh = warpsum(lwh); lobj = warpsum(lobj);
        int wid = tid >> 5, lane = tid & 31;
        if (lane == 0){ s_red[wid][0] = lxy; s_red[wid][1] = lwh; s_red[wid][2] = lobj; }
        __syncthreads();
        if (tid == 0){
            float vx=0.f, vw=0.f, vo=0.f;
            #pragma unroll
            for (int q = 0; q < 8; q++){ vx += s_red[q][0]; vw += s_red[q][1]; vo += s_red[q][2]; }
            partial = make_float4(vx, vw, vo, 0.f);
        }
    }

    // ================= common tail: publish partial, last block reduces =========
    __syncthreads();                    // everyone done with shared state
    if (tid == 0){
        g_part[blockIdx.x] = partial;
        __threadfence();
        unsigned int t = atomicAdd(&g_ticket, 1u);
        s_last = (t == TOTBLK - 1u) ? 1 : 0;
    }
    __syncthreads();
    if (s_last){
        __threadfence();                // acquire: all g_part writes visible
        if (tid < 128){
            int w = tid >> 5, lane = tid & 31;
            const float* P = (const float*)g_part;
            double s = 0.0;
            for (int i = lane; i < TOTBLK; i += 32) s += (double)P[i*4 + w];
            #pragma unroll
            for (int o = 16; o; o >>= 1) s += __shfl_down_sync(0xffffffffu, s, o);
            if (lane == 0) sr[w] = s;
        }
        __syncthreads();
        if (tid == 0){
            double xy = sr[0], wh = sr[1], obj = sr[2], cls = sr[3];
            out[0] = (float)(xy + wh + obj + cls);
            out[1] = (float)xy;
            out[2] = (float)wh;
            out[3] = (float)obj;
            out[4] = (float)cls;
            g_ticket = 0u;              // reset for next graph replay
        }
    }
}

extern "C" void kernel_launch(void* const* d_in, const int* in_sizes, int n_in,
                              void* d_out, int out_size){
    const float* xin    = (const float*)d_in[0];
    const float* labels = (const float*)d_in[1];
    const float* conv_w = (const float*)d_in[2];
    const float* conv_b = (const float*)d_in[3];
    float* out = (float*)d_out;

    k_fused<<<TOTBLK, 256>>>(xin, labels, conv_w, conv_b, out);
}

// round 8
// speedup vs baseline: 1.3887x; 1.3887x over previous
#include <cuda_runtime.h>
#include <math.h>

#define NBATCH 16
#define NANCH  3
#define FS     64
#define NPIX   4096
#define NLAB   50
#define NCLS   80
#define NCH    85
#define CONVBLK 256                 // conv blocks FIRST: blockIdx 0..255
#define CLSBLK (NBATCH*NLAB)        // 800 class-loss blocks after
#define TOTBLK (CONVBLK + CLSBLK)   // 1056

// ---------------- device scratch ----------------
__device__ float4 g_part[TOTBLK];   // per-block partials: x=xy y=wh z=obj w=cls

__constant__ float c_RW[9] = {1.25f,2.0f,4.125f,3.75f,7.75f,7.375f,14.5f,19.5f,46.625f};
__constant__ float c_RH[9] = {1.625f,3.75f,2.875f,7.625f,5.625f,14.875f,11.25f,24.75f,40.75f};

__device__ __forceinline__ float sigm(float x){ return 1.0f/(1.0f + expf(-x)); }

// softplus(o) = max(o,0)+log1p(exp(-|o|));  BCE(sigmoid(o),t) = sp(o) - t*o
__device__ __forceinline__ float sp(float o){
    return fmaxf(o, 0.0f) + log1pf(expf(-fabsf(o)));
}

__device__ __forceinline__ float warpsum(float v){
    #pragma unroll
    for (int o = 16; o; o >>= 1) v += __shfl_down_sync(0xffffffffu, v, o);
    return v;
}

// packed fp32x2 helpers (Blackwell)
__device__ __forceinline__ unsigned long long packff(float a, float b){
    unsigned long long r;
    asm("mov.b64 %0, {%1, %2};" : "=l"(r) : "r"(__float_as_uint(a)), "r"(__float_as_uint(b)));
    return r;
}
__device__ __forceinline__ void unpackff(unsigned long long v, float& a, float& b){
    unsigned int lo, hi;
    asm("mov.b64 {%0, %1}, %2;" : "=r"(lo), "=r"(hi) : "l"(v));
    a = __uint_as_float(lo); b = __uint_as_float(hi);
}
__device__ __forceinline__ void fma2(unsigned long long& acc,
                                     unsigned long long a, unsigned long long b){
    asm("fma.rn.f32x2 %0, %1, %2, %0;" : "+l"(acc) : "l"(a), "l"(b));
}

// one channel's contribution: broadcast x against 16 weights (8 packed FMA2)
__device__ __forceinline__ void chan_fma(unsigned long long* accd,
                                         const ulonglong2* W2, int c, float x){
    unsigned long long xd = packff(x, x);
    ulonglong2 q0 = W2[c*4+0], q1 = W2[c*4+1];
    ulonglong2 q2 = W2[c*4+2], q3 = W2[c*4+3];
    fma2(accd[0], xd, q0.x); fma2(accd[1], xd, q0.y);
    fma2(accd[2], xd, q1.x); fma2(accd[3], xd, q1.y);
    fma2(accd[4], xd, q2.x); fma2(accd[5], xd, q2.y);
    fma2(accd[6], xd, q3.x); fma2(accd[7], xd, q3.y);
}

// candidate cell index for one label (or -1)
__device__ __forceinline__ int label_idx(const float* __restrict__ L,
                                         float& tx, float& ty, float& tw, float& th,
                                         int& bi){
    float cls = L[0], x = L[1], y = L[2], w = L[3], h = L[4];
    tx = x*FS; ty = y*FS; tw = w*FS; th = h*FS;
    float best = -1e30f; bi = 0;
    #pragma unroll
    for (int n = 0; n < 9; n++){
        float inter = fminf(tw, c_RW[n]) * fminf(th, c_RH[n]);
        float uni   = tw*th + c_RW[n]*c_RH[n] - inter;
        float iou   = inter/uni;
        if (iou > best){ best = iou; bi = n; }
    }
    bool valid = (cls + x + y + w + h) > 0.0f;
    if (!(valid && bi < NANCH)) return -1;
    int ti = (int)tx, tj = (int)ty;
    return (bi<<12)|(tj<<6)|ti;
}

// ---------------- fused kernel: 256 conv blocks then 800 cls blocks ----------------
__global__ __launch_bounds__(256, 4) void k_fused(const float* __restrict__ xin,
                                                  const float* __restrict__ labels,
                                                  const float* __restrict__ conv_w,
                                                  const float* __restrict__ conv_b){
    int tid = threadIdx.x;

    if (blockIdx.x >= CONVBLK){
        // ================= class-loss block for label (b, k) =================
        int mb = (int)blockIdx.x - CONVBLK;
        int b  = mb / NLAB, k = mb - b*NLAB;

        __shared__ int   s_idx[NLAB];
        __shared__ int   s_win;
        __shared__ float xs[256];
        __shared__ float s_wred[8];

        if (tid < NLAB){
            float tx,ty,tw,th; int bi;
            s_idx[tid] = label_idx(labels + (size_t)(b*NLAB + tid)*5, tx,ty,tw,th, bi);
        }
        __syncthreads();
        if (tid == 0){
            int idx = s_idx[k];
            if (idx >= 0)
                for (int j = k+1; j < NLAB; j++) if (s_idx[j] == idx) { idx = -1; break; }
            s_win = idx;
        }
        __syncthreads();
        int idx = s_win;
        if (idx < 0){
            if (tid == 0) g_part[blockIdx.x] = make_float4(0.f,0.f,0.f,0.f);
            return;
        }
        int a = idx >> 12, pix = idx & 4095;
        int cls = (int)labels[(size_t)(b*NLAB + k)*5];

        xs[tid] = __ldg(xin + ((size_t)(b*256 + tid))*NPIX + pix);
        __syncthreads();

        int w = tid >> 5, lane = tid & 31;   // 8 warps x 10 classes = 80
        float lc = 0.0f;
        #pragma unroll 2
        for (int t = 0; t < 10; t++){
            int c = w + (t<<3);
            int o = a*NCH + 5 + c;
            const float* wr = conv_w + (size_t)o*256;
            float s = 0.0f;
            #pragma unroll
            for (int i = 0; i < 8; i++) s += xs[lane + (i<<5)]*__ldg(wr + lane + (i<<5));
            s = warpsum(s);
            if (lane == 0){
                s += conv_b[o];
                lc += sp(s) - ((c == cls) ? s : 0.0f);
            }
        }
        if (lane == 0) s_wred[w] = lc;
        __syncthreads();
        if (tid == 0){
            float v = 0.0f;
            #pragma unroll
            for (int q = 0; q < 8; q++) v += s_wred[q];
            g_part[blockIdx.x] = make_float4(0.f, 0.f, 0.f, v);
        }
        return;
    }

    // ================= conv + obj/xy/wh block =================
    int cb  = (int)blockIdx.x;
    int b   = cb >> 4;
    int pix = ((cb & 15) << 8) + tid;

    __shared__ __align__(16) float Ws[256*16];
    __shared__ float4 s_tb[NLAB];
    __shared__ float  s_ta[NLAB];
    __shared__ int    s_idx[NLAB];
    __shared__ int    s_fidx[NLAB];
    __shared__ float4 s_l4[NLAB];
    __shared__ float  s_lt[NLAB];
    __shared__ float  s_bias[16];
    __shared__ float  s_red[8][3];

    for (int i = tid; i < 15*256; i += 256){
        int s = i >> 8, c = i & 255;
        int a = s/5, j = s - a*5;
        Ws[c*16 + s] = conv_w[(a*NCH + j)*256 + c];
    }
    Ws[tid*16 + 15] = 0.0f;
    if (tid >= 224 && tid < 239){ int s = tid-224; int a = s/5; s_bias[s] = conv_b[a*NCH + (s - a*5)]; }
    if (tid == 239) s_bias[15] = 0.0f;
    if (tid < NLAB){
        const float* L = labels + (size_t)(b*NLAB + tid)*5;
        float tx,ty,tw,th; int bi;
        int idx = label_idx(L, tx,ty,tw,th, bi);
        s_idx[tid] = idx;
        s_tb[tid]  = make_float4(tx - tw*0.5f, ty - th*0.5f, tx + tw*0.5f, ty + th*0.5f);
        s_ta[tid]  = tw*th;
        int ti = (int)tx, tj = (int)ty;
        int sb = (bi < NANCH) ? bi : 0;
        s_l4[tid] = make_float4(tx - (float)ti, ty - (float)tj,
                                logf(tw / c_RW[sb] + 1e-16f),
                                logf(th / c_RH[sb] + 1e-16f));
        s_lt[tid] = 2.0f - tw*th*(1.0f/(float)(FS*FS));
    }
    __syncthreads();

    // parallel last-wins winner selection
    if (tid < NLAB){
        int idx = s_idx[tid];
        if (idx >= 0)
            for (int j = tid+1; j < NLAB; j++) if (s_idx[j] == idx) { idx = -1; break; }
        s_fidx[tid] = idx;
    }

    unsigned long long accd[8];
    #pragma unroll
    for (int p = 0; p < 8; p++) accd[p] = packff(s_bias[2*p], s_bias[2*p+1]);

    const float* xp = xin + (size_t)b*256*NPIX + pix;
    const ulonglong2* W2 = reinterpret_cast<const ulonglong2*>(Ws);

    // software-pipelined conv loop: 4 in-flight prefetches while computing 4
    float xv[4], xn[4];
    #pragma unroll
    for (int i = 0; i < 4; i++) xv[i] = __ldg(xp + (size_t)i*NPIX);

    #pragma unroll 1
    for (int c = 0; c < 252; c += 4){
        #pragma unroll
        for (int i = 0; i < 4; i++) xn[i] = __ldg(xp + (size_t)(c + 4 + i)*NPIX);
        #pragma unroll
        for (int i = 0; i < 4; i++) chan_fma(accd, W2, c + i, xv[i]);
        #pragma unroll
        for (int i = 0; i < 4; i++) xv[i] = xn[i];
    }
    #pragma unroll
    for (int i = 0; i < 4; i++) chan_fma(accd, W2, 252 + i, xv[i]);

    float acc[16];
    #pragma unroll
    for (int p = 0; p < 8; p++) unpackff(accd[p], acc[2*p], acc[2*p+1]);
    __syncthreads();   // s_fidx visible

    const float MAW[3] = {1.25f, 2.0f, 4.125f};
    const float MAH[3] = {1.625f, 3.75f, 2.875f};
    float fw = (float)(pix & 63);
    float fh = (float)(pix >> 6);
    float ax0[3], ay0[3], ax1[3], ay1[3], areaA[3];
    #pragma unroll
    for (int a = 0; a < 3; a++){
        float o0 = acc[a*5+0], o1 = acc[a*5+1];
        float o2 = acc[a*5+2], o3 = acc[a*5+3];
        float pw = expf(o2)*MAW[a], ph = expf(o3)*MAH[a];
        float px = sigm(o0) + fw, py = sigm(o1) + fh;
        areaA[a] = pw*ph;
        ax0[a] = px - pw*0.5f; ay0[a] = py - ph*0.5f;
        ax1[a] = px + pw*0.5f; ay1[a] = py + ph*0.5f;
    }

    int ign = 0;
    int msl[3] = {-1,-1,-1};
    for (int kk = 0; kk < NLAB; kk++){
        float4 t = s_tb[kk];
        float ta = s_ta[kk];
        #pragma unroll
        for (int a = 0; a < 3; a++){
            float iw = fmaxf(fminf(ax1[a], t.z) - fmaxf(ax0[a], t.x), 0.0f);
            float ih = fmaxf(fminf(ay1[a], t.w) - fmaxf(ay0[a], t.y), 0.0f);
            float inter = iw*ih;
            float den   = areaA[a] + ta - inter;
            ign |= (inter > 0.7f*den) << a;
        }
        int e = s_fidx[kk];
        if (e >= 0 && (e & 4095) == pix) msl[e >> 12] = kk;
    }

    float lobj = 0.0f, lxy = 0.0f, lwh = 0.0f;
    #pragma unroll
    for (int a = 0; a < 3; a++){
        float o4 = acc[a*5+4];
        int slot = msl[a];
        if (slot >= 0){
            lobj += sp(o4) - o4;
            float4 d = s_l4[slot];
            float ts = s_lt[slot];
            float o0 = acc[a*5+0], o1 = acc[a*5+1];
            lxy += (sp(o0) - d.x*o0 + sp(o1) - d.y*o1)*ts;
            float dw = acc[a*5+2] - d.z, dh = acc[a*5+3] - d.w;
            lwh += (dw*dw + dh*dh)*0.5f*ts;
        } else if (!((ign >> a) & 1)){
            lobj += sp(o4);
        }
    }

    lxy = warpsum(lxy); lwh = warpsum(lwh); lobj = warpsum(lobj);
    int wid = tid >> 5, lane = tid & 31;
    if (lane == 0){ s_red[wid][0] = lxy; s_red[wid][1] = lwh; s_red[wid][2] = lobj; }
    __syncthreads();
    if (tid == 0){
        float vx=0.f, vw=0.f, vo=0.f;
        #pragma unroll
        for (int q = 0; q < 8; q++){ vx += s_red[q][0]; vw += s_red[q][1]; vo += s_red[q][2]; }
        g_part[blockIdx.x] = make_float4(vx, vw, vo, 0.f);
    }
}

// ---------------- finalize: reduce per-block partials ----------------
__global__ __launch_bounds__(128) void k_final(float* __restrict__ out){
    int w = threadIdx.x >> 5, lane = threadIdx.x & 31;
    const float* P = (const float*)g_part;
    double s = 0.0;
    for (int i = lane; i < TOTBLK; i += 32) s += (double)P[i*4 + w];
    #pragma unroll
    for (int o = 16; o; o >>= 1) s += __shfl_down_sync(0xffffffffu, s, o);
    __shared__ double sr[4];
    if (lane == 0) sr[w] = s;
    __syncthreads();
    if (threadIdx.x == 0){
        double xy = sr[0], wh = sr[1], obj = sr[2], cls = sr[3];
        out[0] = (float)(xy + wh + obj + cls);
        out[1] = (float)xy;
        out[2] = (float)wh;
        out[3] = (float)obj;
        out[4] = (float)cls;
    }
}

extern "C" void kernel_launch(void* const* d_in, const int* in_sizes, int n_in,
                              void* d_out, int out_size){
    const float* xin    = (const float*)d_in[0];
    const float* labels = (const float*)d_in[1];
    const float* conv_w = (const float*)d_in[2];
    const float* conv_b = (const float*)d_in[3];
    float* out = (float*)d_out;

    k_fused<<<TOTBLK, 256>>>(xin, labels, conv_w, conv_b);
    k_final<<<1, 128>>>(out);
}